// round 2
// baseline (speedup 1.0000x reference)
#include <cuda_runtime.h>
#include <math.h>

// Problem constants
#define B_  8
#define A_  6
#define QS_ 32
#define KS_ 1024
#define C_  256
#define H_  64
#define W_DIM 64
#define NSPAT (C_ * H_ * W_DIM)      // 1048576 per (b, agent)
#define N4 (NSPAT / 4)               // 262144 float4 per (b, agent)
#define OUT_MAIN ((size_t)B_ * A_ * NSPAT)  // 50331648

// scratch for the 8 x 6 x 6 softmaxed attention (allocation-free: device global)
__device__ float g_attn[B_ * A_ * A_];

// --------------------------------------------------------------------------
// Kernel 1: attention scores + softmax, via the transposed projection:
//   attn[k,q] = sum_j qu[q,j] * kp[k,j] + kb[k]
//   kp[b,k,j] = sum_d k[b,k,d] * W[d,j]   (lane j -> coalesced W reads)
//   kb[b,k]   = sum_d k[b,k,d] * bias[d]
// One block per batch, 6 warps (one per key-agent).
// --------------------------------------------------------------------------
__global__ void __launch_bounds__(192)
attn_small_kernel(const float* __restrict__ qu,   // [B, A, QS]
                  const float* __restrict__ kmat, // [B, A, KS]
                  const float* __restrict__ Wm,   // [KS, QS]
                  const float* __restrict__ bias, // [KS]
                  float* __restrict__ out_tail,   // [B, A, A] or null
                  int write_tail) {
    const int b    = blockIdx.x;
    const int tid  = threadIdx.x;
    const int warp = tid >> 5;          // 0..5 == key agent kk
    const int lane = tid & 31;          // 0..31 == j

    __shared__ float s_kp[A_][QS_];     // 6 x 32
    __shared__ float s_kb[A_];
    __shared__ float s_attn[A_ * A_];

    const float* __restrict__ krow = kmat + ((size_t)b * A_ + warp) * KS_;

    // kp[warp][lane] = sum_d k[d] * W[d*32 + lane]  -- W reads coalesced per warp
    float acc = 0.f;
    #pragma unroll 4
    for (int d = 0; d < KS_; d++) {
        acc = fmaf(krow[d], Wm[d * QS_ + lane], acc);
    }
    s_kp[warp][lane] = acc;

    // kb[warp] = sum_d k[d] * bias[d]  (lane-strided, coalesced)
    float s = 0.f;
    for (int d = lane; d < KS_; d += 32)
        s = fmaf(krow[d], bias[d], s);
    #pragma unroll
    for (int off = 16; off; off >>= 1)
        s += __shfl_down_sync(0xffffffffu, s, off);
    if (lane == 0) s_kb[warp] = s;
    __syncthreads();

    // attn[kk][qq] = dot32(s_kp[kk], qu[b,qq,:]) + kb[kk]   (36 threads)
    if (tid < A_ * A_) {
        const int kk = tid / A_, qq = tid % A_;
        const float* __restrict__ qrow = qu + ((size_t)b * A_ + qq) * QS_;
        float v = s_kb[kk];
        #pragma unroll
        for (int j = 0; j < QS_; j++) v = fmaf(s_kp[kk][j], qrow[j], v);
        s_attn[kk * A_ + qq] = v;
    }
    __syncthreads();

    // softmax over kk (axis=1 of [B, K, Q]) for each qq
    if (tid < A_) {
        const int qq = tid;
        float m = -INFINITY;
        #pragma unroll
        for (int kk = 0; kk < A_; kk++) m = fmaxf(m, s_attn[kk * A_ + qq]);
        float e[A_], sum = 0.f;
        #pragma unroll
        for (int kk = 0; kk < A_; kk++) {
            e[kk] = expf(s_attn[kk * A_ + qq] - m);
            sum += e[kk];
        }
        const float inv = 1.f / sum;
        #pragma unroll
        for (int kk = 0; kk < A_; kk++) {
            const float a = e[kk] * inv;
            g_attn[b * 36 + kk * A_ + qq] = a;
            if (write_tail) out_tail[b * 36 + kk * A_ + qq] = a;
        }
    }
}

// --------------------------------------------------------------------------
// Kernel 2: out[b,q,x] = sum_k attn_sm[b,k,q] * v[b,k,x]  (x = c*h*w flat)
// HBM-bound streaming: 6 float4 loads -> 6 float4 stores per thread.
// (ncu R1: 79% DRAM, 6255 GB/s — near roofline; unchanged.)
// --------------------------------------------------------------------------
__global__ void __launch_bounds__(256)
combine_kernel(const float4* __restrict__ v, float4* __restrict__ out) {
    const int b = blockIdx.y;
    const int x = blockIdx.x * blockDim.x + threadIdx.x;   // 0 .. N4-1

    __shared__ float s_a[A_ * A_];
    if (threadIdx.x < A_ * A_) s_a[threadIdx.x] = g_attn[b * 36 + threadIdx.x];
    __syncthreads();

    float4 vv[A_];
    #pragma unroll
    for (int kk = 0; kk < A_; kk++)
        vv[kk] = v[((size_t)(b * A_ + kk)) * N4 + x];

    #pragma unroll
    for (int qq = 0; qq < A_; qq++) {
        float4 o = make_float4(0.f, 0.f, 0.f, 0.f);
        #pragma unroll
        for (int kk = 0; kk < A_; kk++) {
            const float a = s_a[kk * A_ + qq];
            o.x = fmaf(a, vv[kk].x, o.x);
            o.y = fmaf(a, vv[kk].y, o.y);
            o.z = fmaf(a, vv[kk].z, o.z);
            o.w = fmaf(a, vv[kk].w, o.w);
        }
        out[((size_t)(b * A_ + qq)) * N4 + x] = o;
    }
}

extern "C" void kernel_launch(void* const* d_in, const int* in_sizes, int n_in,
                              void* d_out, int out_size) {
    const float* qu   = (const float*)d_in[0];   // [8,6,32]
    const float* kmat = (const float*)d_in[1];   // [8,6,1024]
    const float* v    = (const float*)d_in[2];   // [8,6,256,64,64]
    const float* Wm   = (const float*)d_in[3];   // [1024,32]
    const float* bias = (const float*)d_in[4];   // [1024]

    float* out = (float*)d_out;
    const int write_tail = ((size_t)out_size >= OUT_MAIN + (size_t)B_ * 36) ? 1 : 0;
    float* out_tail = out + OUT_MAIN;

    attn_small_kernel<<<B_, 192>>>(qu, kmat, Wm, bias, out_tail, write_tail);

    dim3 grid(N4 / 256, B_);
    combine_kernel<<<grid, 256>>>((const float4*)v, (float4*)out);
}

// round 3
// speedup vs baseline: 2.5961x; 2.5961x over previous
#include <cuda_runtime.h>
#include <math.h>

// Problem constants
#define B_  8
#define A_  6
#define QS_ 32
#define KS_ 1024
#define C_  256
#define H_  64
#define W_DIM 64
#define NSPAT (C_ * H_ * W_DIM)            // 1048576 per (b, agent)
#define N4 (NSPAT / 4)                     // 262144 float4 per (b, agent)
#define OUT_MAIN ((size_t)B_ * A_ * NSPAT) // 50331648

#define CHUNKS 16
#define DCH (KS_ / CHUNKS)                 // 64 d-values per chunk

// Allocation-free scratch (device globals)
__device__ float g_attn[B_ * A_ * A_];                      // softmaxed attention
__device__ float g_kp_part[CHUNKS * B_ * A_ * QS_];         // partial k@W

// --------------------------------------------------------------------------
// Kernel A: partial kp[b,k,j] = sum_{d in chunk c} k[b,k,d] * W[d,j]
// Grid (CHUNKS, B). Bulk float4 loads into smem -> massive MLP, latency hidden.
// --------------------------------------------------------------------------
__global__ void __launch_bounds__(256)
kp_partial_kernel(const float* __restrict__ kmat,  // [B, A, KS]
                  const float* __restrict__ Wm) {  // [KS, QS]
    const int c = blockIdx.x;   // d-chunk
    const int b = blockIdx.y;   // batch
    const int tid = threadIdx.x;

    __shared__ float s_W[DCH * QS_];   // 64 x 32 = 8 KB
    __shared__ float s_k[A_][DCH];     // 6 x 64

    // Load W chunk (2048 floats = 512 float4; 2 per thread, coalesced)
    const float4* __restrict__ Wg = (const float4*)(Wm + (size_t)c * DCH * QS_);
    float4* sW4 = (float4*)s_W;
    #pragma unroll
    for (int i = tid; i < DCH * QS_ / 4; i += 256) sW4[i] = Wg[i];

    // Load k chunk (384 floats)
    for (int i = tid; i < A_ * DCH; i += 256) {
        const int kk = i / DCH, dd = i % DCH;
        s_k[kk][dd] = kmat[((size_t)b * A_ + kk) * KS_ + c * DCH + dd];
    }
    __syncthreads();

    // 192 threads: (kk, j) each. s_k broadcast within warp, s_W lane j -> bank j.
    if (tid < A_ * QS_) {
        const int kk = tid >> 5, j = tid & 31;
        float acc = 0.f;
        #pragma unroll
        for (int dd = 0; dd < DCH; dd++)
            acc = fmaf(s_k[kk][dd], s_W[dd * QS_ + j], acc);
        g_kp_part[(((size_t)c * B_ + b) * A_ + kk) * QS_ + j] = acc;
    }
}

// --------------------------------------------------------------------------
// Kernel B: reduce kp partials, kb = k.bias, scores, softmax. Grid B_, 192 thr.
// --------------------------------------------------------------------------
__global__ void __launch_bounds__(192)
attn_finish_kernel(const float* __restrict__ qu,    // [B, A, QS]
                   const float* __restrict__ kmat,  // [B, A, KS]
                   const float* __restrict__ bias,  // [KS]
                   float* __restrict__ out_tail,    // [B, A, A]
                   int write_tail) {
    const int b = blockIdx.x;
    const int tid = threadIdx.x;
    const int warp = tid >> 5, lane = tid & 31;

    __shared__ float s_kp[A_][QS_];
    __shared__ float s_kb[A_];
    __shared__ float s_qu[A_ * QS_];   // 192 floats
    __shared__ float s_attn[A_ * A_];

    // qu for this batch (exactly 192 floats, one per thread)
    s_qu[tid] = qu[(size_t)b * A_ * QS_ + tid];

    // Reduce 16 kp partials (L2-hot: just written by kernel A)
    {
        float acc = 0.f;
        #pragma unroll
        for (int c = 0; c < CHUNKS; c++)
            acc += g_kp_part[(((size_t)c * B_ + b) * A_ + warp) * QS_ + lane];
        s_kp[warp][lane] = acc;
    }

    // kb[warp] = dot(k[b,warp,:], bias) via fully-unrolled float4 loads (MLP 8)
    {
        const float4* __restrict__ k4 = (const float4*)(kmat + ((size_t)b * A_ + warp) * KS_);
        const float4* __restrict__ b4 = (const float4*)bias;
        float s = 0.f;
        #pragma unroll
        for (int i = 0; i < KS_ / 4 / 32; i++) {   // 8 iters
            const float4 kv = k4[lane + 32 * i];
            const float4 bv = b4[lane + 32 * i];
            s += kv.x * bv.x + kv.y * bv.y + kv.z * bv.z + kv.w * bv.w;
        }
        #pragma unroll
        for (int off = 16; off; off >>= 1)
            s += __shfl_down_sync(0xffffffffu, s, off);
        if (lane == 0) s_kb[warp] = s;
    }
    __syncthreads();

    // scores[kk][qq] = kb[kk] + dot32(kp[kk], qu[qq])
    if (tid < A_ * A_) {
        const int kk = tid / A_, qq = tid % A_;
        float v = s_kb[kk];
        #pragma unroll
        for (int j = 0; j < QS_; j++)
            v = fmaf(s_kp[kk][j], s_qu[qq * QS_ + j], v);
        s_attn[kk * A_ + qq] = v;
    }
    __syncthreads();

    // softmax over kk for each qq
    if (tid < A_) {
        const int qq = tid;
        float m = -INFINITY;
        #pragma unroll
        for (int kk = 0; kk < A_; kk++) m = fmaxf(m, s_attn[kk * A_ + qq]);
        float e[A_], sum = 0.f;
        #pragma unroll
        for (int kk = 0; kk < A_; kk++) {
            e[kk] = expf(s_attn[kk * A_ + qq] - m);
            sum += e[kk];
        }
        const float inv = 1.f / sum;
        #pragma unroll
        for (int kk = 0; kk < A_; kk++) {
            const float a = e[kk] * inv;
            g_attn[b * 36 + kk * A_ + qq] = a;
            if (write_tail) out_tail[b * 36 + kk * A_ + qq] = a;
        }
    }
}

// --------------------------------------------------------------------------
// Kernel C: out[b,q,x] = sum_k attn_sm[b,k,q] * v[b,k,x]  -- UNCHANGED
// (ncu: 78% DRAM, ~6.2 TB/s -- near streaming roofline)
// --------------------------------------------------------------------------
__global__ void __launch_bounds__(256)
combine_kernel(const float4* __restrict__ v, float4* __restrict__ out) {
    const int b = blockIdx.y;
    const int x = blockIdx.x * blockDim.x + threadIdx.x;   // 0 .. N4-1

    __shared__ float s_a[A_ * A_];
    if (threadIdx.x < A_ * A_) s_a[threadIdx.x] = g_attn[b * 36 + threadIdx.x];
    __syncthreads();

    float4 vv[A_];
    #pragma unroll
    for (int kk = 0; kk < A_; kk++)
        vv[kk] = v[((size_t)(b * A_ + kk)) * N4 + x];

    #pragma unroll
    for (int qq = 0; qq < A_; qq++) {
        float4 o = make_float4(0.f, 0.f, 0.f, 0.f);
        #pragma unroll
        for (int kk = 0; kk < A_; kk++) {
            const float a = s_a[kk * A_ + qq];
            o.x = fmaf(a, vv[kk].x, o.x);
            o.y = fmaf(a, vv[kk].y, o.y);
            o.z = fmaf(a, vv[kk].z, o.z);
            o.w = fmaf(a, vv[kk].w, o.w);
        }
        out[((size_t)(b * A_ + qq)) * N4 + x] = o;
    }
}

extern "C" void kernel_launch(void* const* d_in, const int* in_sizes, int n_in,
                              void* d_out, int out_size) {
    const float* qu   = (const float*)d_in[0];   // [8,6,32]
    const float* kmat = (const float*)d_in[1];   // [8,6,1024]
    const float* v    = (const float*)d_in[2];   // [8,6,256,64,64]
    const float* Wm   = (const float*)d_in[3];   // [1024,32]
    const float* bias = (const float*)d_in[4];   // [1024]

    float* out = (float*)d_out;
    const int write_tail = ((size_t)out_size >= OUT_MAIN + (size_t)B_ * 36) ? 1 : 0;
    float* out_tail = out + OUT_MAIN;

    dim3 gridA(CHUNKS, B_);
    kp_partial_kernel<<<gridA, 256>>>(kmat, Wm);

    attn_finish_kernel<<<B_, 192>>>(qu, kmat, bias, out_tail, write_tail);

    dim3 gridC(N4 / 256, B_);
    combine_kernel<<<gridC, 256>>>((const float4*)v, (float4*)out);
}